// round 9
// baseline (speedup 1.0000x reference)
#include <cuda_runtime.h>

#define TB      32      // batch elements per CTA
#define THREADS 384     // 3 agents x 32 h-groups(4h) x 4 e-groups(8e)

// smem float offsets
#define OFF_IN    0                     // [3][TB][40]  obs(30)+act(9)+pad
#define OFF_OEMB  (3*TB*40)             // [3][TB][128] o_emb (persists)
#define OFF_OA    (OFF_OEMB + 3*TB*128) // [3][TB][128] oa_emb -> Q -> attn_out
#define OFF_K     (OFF_OA   + 3*TB*128) // [3][TB][128] K, reused as h1
#define OFF_V     (OFF_K    + 3*TB*128) // [3][TB][128] V
#define SMEM_FLOATS (OFF_V + 3*TB*128)  // 52992 floats = 207 KB

// acc[e] (.x..w = h0..h0+3) += sum_k in[e][k] * W[k*128 + h0+c]
// sp: smem ptr to in[e=0][k=0] (warp-uniform address -> broadcast LDS.128).
// Wp = W + h0 (lane-varying, 512B/warp contiguous -> coalesced LDG.128).
// Weight rows >= KVALID treated as zero.
template<int NQ, int KVALID, int ESTRIDE>
__device__ __forceinline__ void gemm48(const float* __restrict__ sp,
                                       const float* __restrict__ Wp,
                                       float4 acc[8])
{
    #pragma unroll 8
    for (int q = 0; q < NQ; q++) {
        const int k = q * 4;
        const float4 z = make_float4(0.f, 0.f, 0.f, 0.f);
        float4 w0 = (k+0 < KVALID) ? *(const float4*)(Wp + (k+0)*128) : z;
        float4 w1 = (k+1 < KVALID) ? *(const float4*)(Wp + (k+1)*128) : z;
        float4 w2 = (k+2 < KVALID) ? *(const float4*)(Wp + (k+2)*128) : z;
        float4 w3 = (k+3 < KVALID) ? *(const float4*)(Wp + (k+3)*128) : z;
        #pragma unroll
        for (int e = 0; e < 8; e++) {
            const float4 x = *(const float4*)(sp + e*ESTRIDE + k);
            float4 a = acc[e];
            a.x = fmaf(x.x, w0.x, a.x); a.y = fmaf(x.x, w0.y, a.y);
            a.z = fmaf(x.x, w0.z, a.z); a.w = fmaf(x.x, w0.w, a.w);
            a.x = fmaf(x.y, w1.x, a.x); a.y = fmaf(x.y, w1.y, a.y);
            a.z = fmaf(x.y, w1.z, a.z); a.w = fmaf(x.y, w1.w, a.w);
            a.x = fmaf(x.z, w2.x, a.x); a.y = fmaf(x.z, w2.y, a.y);
            a.z = fmaf(x.z, w2.z, a.z); a.w = fmaf(x.z, w2.w, a.w);
            a.x = fmaf(x.w, w3.x, a.x); a.y = fmaf(x.w, w3.y, a.y);
            a.z = fmaf(x.w, w3.z, a.z); a.w = fmaf(x.w, w3.w, a.w);
            acc[e] = a;
        }
    }
}

__device__ __forceinline__ float4 leaky4(float4 v) {
    v.x = (v.x >= 0.f) ? v.x : 0.01f * v.x;
    v.y = (v.y >= 0.f) ? v.y : 0.01f * v.y;
    v.z = (v.z >= 0.f) ? v.z : 0.01f * v.z;
    v.w = (v.w >= 0.f) ? v.w : 0.01f * v.w;
    return v;
}

__global__ __launch_bounds__(THREADS)
void valuenet_kernel(
    const float* __restrict__ obs,  const float* __restrict__ act,
    const float* __restrict__ W_o,  const float* __restrict__ b_o,
    const float* __restrict__ W_oa, const float* __restrict__ b_oa,
    const float* __restrict__ Wq,   const float* __restrict__ bq,
    const float* __restrict__ Wk,   const float* __restrict__ bk,
    const float* __restrict__ Wv,   const float* __restrict__ bv,
    const float* __restrict__ Wc1,  const float* __restrict__ bc1,
    const float* __restrict__ Wc2,  const float* __restrict__ bc2,
    float* __restrict__ out)
{
    extern __shared__ float sm[];
    float* s_in   = sm + OFF_IN;
    float* s_oemb = sm + OFF_OEMB;
    float* s_oa   = sm + OFF_OA;   // oa_emb -> Q -> attn_out
    float* s_K    = sm + OFF_K;    // K, later h1
    float* s_V    = sm + OFF_V;

    const int t   = threadIdx.x;
    const int n   = t >> 7;        // agent 0..2 (uniform per warp)
    const int r   = t & 127;
    const int hg  = r & 31;        // h-group (4 channels)
    const int eg  = r >> 5;        // e-group 0..3 (uniform per warp)
    const int h0  = hg * 4;
    const int eb  = eg * 8;
    const int e0g = blockIdx.x * TB;

    // ---------------- P0: stage inputs ----------------
    for (int i = t; i < TB * 90; i += THREADS) {
        int e = i / 90, rr = i - e * 90;
        int nn = rr / 30, d = rr - nn * 30;
        s_in[(nn * TB + e) * 40 + d] = obs[(long)(e0g + e) * 90 + rr];
    }
    for (int i = t; i < TB * 27; i += THREADS) {
        int e = i / 27, rr = i - e * 27;
        int nn = rr / 9, d = rr - nn * 9;
        s_in[(nn * TB + e) * 40 + 30 + d] = act[(long)(e0g + e) * 27 + rr];
    }
    for (int i = t; i < 3 * TB; i += THREADS) s_in[i * 40 + 39] = 0.f;  // pad
    __syncthreads();

    // ---------------- P1: per-agent embeds ----------------
    {
        const float* sp = s_in + (n * TB + eb) * 40;
        {   // o_emb
            float4 acc[8];
            const float4 b = *(const float4*)(b_o + n*128 + h0);
            #pragma unroll
            for (int e = 0; e < 8; e++) acc[e] = b;
            gemm48<8, 30, 40>(sp, W_o + n * 30 * 128 + h0, acc);
            #pragma unroll
            for (int e = 0; e < 8; e++)
                *(float4*)&s_oemb[(n*TB + eb + e)*128 + h0] = leaky4(acc[e]);
        }
        {   // oa_emb
            float4 acc[8];
            const float4 b = *(const float4*)(b_oa + n*128 + h0);
            #pragma unroll
            for (int e = 0; e < 8; e++) acc[e] = b;
            gemm48<10, 39, 40>(sp, W_oa + n * 39 * 128 + h0, acc);
            #pragma unroll
            for (int e = 0; e < 8; e++)
                *(float4*)&s_oa[(n*TB + eb + e)*128 + h0] = leaky4(acc[e]);
        }
    }
    __syncthreads();

    // ---------------- P2a: K and V projections (read oa_emb) ----------------
    {
        const float* spA = s_oa + (n * TB + eb) * 128;
        {   // K
            float4 acc[8];
            const float4 b = *(const float4*)(bk + h0);
            #pragma unroll
            for (int e = 0; e < 8; e++) acc[e] = b;
            gemm48<32, 128, 128>(spA, Wk + h0, acc);
            #pragma unroll
            for (int e = 0; e < 8; e++)
                *(float4*)&s_K[(n*TB + eb + e)*128 + h0] = acc[e];
        }
        {   // V
            float4 acc[8];
            const float4 b = *(const float4*)(bv + h0);
            #pragma unroll
            for (int e = 0; e < 8; e++) acc[e] = b;
            gemm48<32, 128, 128>(spA, Wv + h0, acc);
            #pragma unroll
            for (int e = 0; e < 8; e++)
                *(float4*)&s_V[(n*TB + eb + e)*128 + h0] = acc[e];
        }
    }
    __syncthreads();   // everyone done reading oa_emb; K,V visible

    // ---------------- P2b: Q projection (oa region becomes Q) ----------------
    {
        const float* spQ = s_oemb + (n * TB + eb) * 128;
        float4 acc[8];
        const float4 b = *(const float4*)(bq + h0);
        #pragma unroll
        for (int e = 0; e < 8; e++) acc[e] = b;
        gemm48<32, 128, 128>(spQ, Wq + h0, acc);
        #pragma unroll
        for (int e = 0; e < 8; e++)
            *(float4*)&s_oa[(n*TB + eb + e)*128 + h0] = acc[e];   // Q in-place
    }
    // no sync needed: attention reads Q only from this thread's own slots,
    // and K/V were made visible by the previous barrier.

    // ---------------- P3: 3-agent masked attention ----------------
    // head = hg>>3 (8 lanes x 4 dims = 32 head dims); xor-shuffle over 8 lanes.
    {
        const float scale = 0.17677669529663689f;  // 1/sqrt(32)
        #pragma unroll
        for (int ei = 0; ei < 8; ei++) {
            const int e = eb + ei;
            float4 q  = *(float4*)&s_oa[(n*TB + e)*128 + h0];
            float4 k0 = *(float4*)&s_K[(0*TB + e)*128 + h0];
            float4 k1 = *(float4*)&s_K[(1*TB + e)*128 + h0];
            float4 k2 = *(float4*)&s_K[(2*TB + e)*128 + h0];
            float s0 = q.x*k0.x + q.y*k0.y + q.z*k0.z + q.w*k0.w;
            float s1 = q.x*k1.x + q.y*k1.y + q.z*k1.z + q.w*k1.w;
            float s2 = q.x*k2.x + q.y*k2.y + q.z*k2.z + q.w*k2.w;
            #pragma unroll
            for (int off = 4; off > 0; off >>= 1) {
                s0 += __shfl_xor_sync(0xffffffffu, s0, off);
                s1 += __shfl_xor_sync(0xffffffffu, s1, off);
                s2 += __shfl_xor_sync(0xffffffffu, s2, off);
            }
            s0 *= scale; s1 *= scale; s2 *= scale;
            if (n == 0)      s0 -= 1e10f;
            else if (n == 1) s1 -= 1e10f;
            else             s2 -= 1e10f;
            float mx  = fmaxf(s0, fmaxf(s1, s2));
            float p0  = __expf(s0 - mx);
            float p1  = __expf(s1 - mx);
            float p2  = __expf(s2 - mx);
            float inv = 1.0f / (p0 + p1 + p2);
            p0 *= inv; p1 *= inv; p2 *= inv;
            float4 v0 = *(float4*)&s_V[(0*TB + e)*128 + h0];
            float4 v1 = *(float4*)&s_V[(1*TB + e)*128 + h0];
            float4 v2 = *(float4*)&s_V[(2*TB + e)*128 + h0];
            float4 ao;
            ao.x = p0*v0.x + p1*v1.x + p2*v2.x;
            ao.y = p0*v0.y + p1*v1.y + p2*v2.y;
            ao.z = p0*v0.z + p1*v1.z + p2*v2.z;
            ao.w = p0*v0.w + p1*v1.w + p2*v2.w;
            *(float4*)&s_oa[(n*TB + e)*128 + h0] = ao;   // attn_out in-place
        }
    }
    __syncthreads();

    // ---------------- P4: critic layer 1 (256 -> 128) ----------------
    {
        float4 acc[8];
        const float4 b = *(const float4*)(bc1 + n*128 + h0);
        #pragma unroll
        for (int e = 0; e < 8; e++) acc[e] = b;
        gemm48<32, 128, 128>(s_oemb + (n*TB + eb) * 128,
                             Wc1 + (size_t)n * 256 * 128 + h0, acc);
        gemm48<32, 128, 128>(s_oa + (n*TB + eb) * 128,
                             Wc1 + ((size_t)n * 256 + 128) * 128 + h0, acc);
        #pragma unroll
        for (int e = 0; e < 8; e++)
            *(float4*)&s_K[(n*TB + eb + e)*128 + h0] = leaky4(acc[e]);  // h1
    }
    __syncthreads();

    // ---------------- P5: critic layer 2 (128 -> 9) + store ----------------
    for (int idx = t; idx < TB * 27; idx += THREADS) {
        int e = idx / 27, rr = idx - e * 27;
        int nn = rr / 9,  a = rr - nn * 9;
        float acc = bc2[nn * 9 + a];
        const float* hp = &s_K[(nn * TB + e) * 128];
        const float* wp = Wc2 + (size_t)nn * 128 * 9 + a;
        #pragma unroll 8
        for (int j = 0; j < 128; j += 4) {
            float4 x = *(const float4*)(hp + j);
            acc += x.x * wp[(j+0)*9] + x.y * wp[(j+1)*9]
                 + x.z * wp[(j+2)*9] + x.w * wp[(j+3)*9];
        }
        out[(long)(e0g + e) * 27 + rr] = acc;
    }
}

extern "C" void kernel_launch(void* const* d_in, const int* in_sizes, int n_in,
                              void* d_out, int out_size) {
    const float* obs  = (const float*)d_in[0];
    const float* act  = (const float*)d_in[1];
    const float* W_o  = (const float*)d_in[2];
    const float* b_o  = (const float*)d_in[3];
    const float* W_oa = (const float*)d_in[4];
    const float* b_oa = (const float*)d_in[5];
    const float* Wq   = (const float*)d_in[6];
    const float* bq   = (const float*)d_in[7];
    const float* Wk   = (const float*)d_in[8];
    const float* bk   = (const float*)d_in[9];
    const float* Wv   = (const float*)d_in[10];
    const float* bv   = (const float*)d_in[11];
    const float* Wc1  = (const float*)d_in[12];
    const float* bc1  = (const float*)d_in[13];
    const float* Wc2  = (const float*)d_in[14];
    const float* bc2  = (const float*)d_in[15];
    float* out = (float*)d_out;

    const int batch = in_sizes[0] / (3 * 30);   // 131072
    const int grid  = batch / TB;               // 4096
    const size_t smem = SMEM_FLOATS * sizeof(float);  // 207 KB

    cudaFuncSetAttribute(valuenet_kernel,
                         cudaFuncAttributeMaxDynamicSharedMemorySize, (int)smem);
    valuenet_kernel<<<grid, THREADS, smem>>>(
        obs, act, W_o, b_o, W_oa, b_oa, Wq, bq, Wk, bk, Wv, bv,
        Wc1, bc1, Wc2, bc2, out);
}